// round 4
// baseline (speedup 1.0000x reference)
#include <cuda_runtime.h>
#include <cuda_bf16.h>
#include <math.h>

// ---------------- problem constants ----------------
#define Bsz   64
#define Nn    256
#define CT    3
#define HID   256
#define HEADS 4
#define Ch    64
#define Eg    8192
#define F_IN  (Nn*CT)
#define ROWS  (Bsz*Nn)
#define NEGS  0.2f
#define EPSBN 1e-5f

// ---------------- scratch ----------------
__device__ float g_h [ROWS*HID];
__device__ float g_xl[ROWS*HID];
__device__ float g_xr[ROWS*HID];
__device__ float g_h2[ROWS*HID];
__device__ float g_pool[Bsz*HID];
__device__ int   g_off[Nn+1];
__device__ int   g_srce[Eg];
__device__ int   g_dste[Eg];

__device__ __forceinline__ float gelu_exact(float x) { return x * normcdff(x); }

__device__ __forceinline__ unsigned f2tf32(float f) {
    unsigned u;
    asm("cvt.rna.tf32.f32 %0, %1;" : "=r"(u) : "f"(f));
    return u;
}

__device__ __forceinline__ void mma_tf32(float* c, const unsigned* a, const unsigned* b) {
    asm("mma.sync.aligned.m16n8k8.row.col.f32.tf32.tf32.f32 "
        "{%0,%1,%2,%3},{%4,%5,%6,%7},{%8,%9},{%0,%1,%2,%3};"
        : "+f"(c[0]), "+f"(c[1]), "+f"(c[2]), "+f"(c[3])
        : "r"(a[0]), "r"(a[1]), "r"(a[2]), "r"(a[3]), "r"(b[0]), "r"(b[1]));
}

// ---------------- deterministic CSR build ----------------
__global__ __launch_bounds__(256)
void build_csr_kernel(const int* __restrict__ ei,
                      int* __restrict__ off,
                      int* __restrict__ srce, int* __restrict__ dste) {
    __shared__ int hist[8][Nn];
    __shared__ int s_loc[Eg];
    __shared__ int s_off[Nn+1];

    const int tid  = threadIdx.x;
    const int w    = tid >> 5;
    const int lane = tid & 31;
    const int* srcA = ei;
    const int* dstA = ei + Eg;

    for (int i = tid; i < 8 * Nn; i += 256) ((int*)hist)[i] = 0;
    __syncthreads();

    const int base = w * 1024;
#pragma unroll 1
    for (int g = 0; g < 32; g++) {
        const int e = base + g * 32 + lane;
        const int d = dstA[e];
        unsigned mask = __match_any_sync(0xffffffffu, d);
        int leader = __ffs(mask) - 1;
        int rank   = __popc(mask & ((1u << lane) - 1u));
        int cur    = hist[w][d];
        s_loc[e]   = cur + rank;
        __syncwarp();
        if (lane == leader) hist[w][d] = cur + __popc(mask);
        __syncwarp();
    }
    __syncthreads();

    __shared__ int tot[Nn];
    if (tid < Nn) {
        int run = 0;
#pragma unroll
        for (int ww = 0; ww < 8; ww++) {
            int c = hist[ww][tid];
            hist[ww][tid] = run;
            run += c;
        }
        tot[tid] = run;
    }
    __syncthreads();
    if (tid == 0) {
        int run = 0;
        for (int n = 0; n < Nn; n++) { s_off[n] = run; run += tot[n]; }
        s_off[Nn] = run;
    }
    __syncthreads();

    if (tid < Nn) off[tid] = s_off[tid];
    if (tid == 0) off[Nn] = s_off[Nn];

    for (int e = tid; e < Eg; e += 256) {
        const int d  = dstA[e];
        const int we = e >> 10;
        const int pos = s_off[d] + hist[we][d] + s_loc[e];
        srce[pos] = srcA[e];
        dste[pos] = d;
    }
}

// ---------------- tensor-core GEMM (3xTF32, fp32-accurate) ----------------
// CTA 128x128, k-chunk 32, 256 threads = 8 warps (4m x 2n), warp tile 32x64.
// smem: A[2][128][36] (m-major, stride 36 -> conflict-free frag LDS)
//       B[2][32][136]  (k-major, stride 136 -> conflict-free frag LDS)
#define AS_STR 36
#define BS_STR 136
#define AS_FLOATS (128*AS_STR)
#define BS_FLOATS (32*BS_STR)
#define TG_SMEM ((2*AS_FLOATS + 2*BS_FLOATS) * 4)

__global__ __launch_bounds__(256)
void tgemm_kernel(const float* __restrict__ A,
                  const float* __restrict__ B,  const float* __restrict__ bias,  float* __restrict__ C,
                  const float* __restrict__ B2, const float* __restrict__ bias2, float* __restrict__ C2,
                  int M, int N, int K,
                  const float* __restrict__ gam, const float* __restrict__ bet,
                  const float* __restrict__ mu,  const float* __restrict__ var,
                  int epi, int dual)
{
    extern __shared__ float sm[];
    float* As = sm;                      // 2 * 128*36
    float* Bs = sm + 2*AS_FLOATS;        // 2 * 32*136

    const int tid  = threadIdx.x;
    const int warp = tid >> 5;
    const int lane = tid & 31;
    int bx = blockIdx.x;
    const int nblk = dual ? (gridDim.x >> 1) : gridDim.x;
    if (dual && bx >= nblk) {
        bx -= nblk;
        B = B2; bias = bias2; C = C2;
    }
    const int cb = bx * 128;
    const int rb = blockIdx.y * 128;

    const int m_w = (warp & 3) * 32;    // warp m offset in tile
    const int n_w = (warp >> 2) * 64;   // warp n offset in tile

    float acc[2][8][4];
#pragma unroll
    for (int mt = 0; mt < 2; mt++)
#pragma unroll
        for (int nt = 0; nt < 8; nt++)
#pragma unroll
            for (int i = 0; i < 4; i++) acc[mt][nt][i] = 0.f;

    // loader indices
    const int a_r  = tid >> 3;          // 0..31 (+32*it)
    const int a_kq = (tid & 7) * 4;
    const int b_k  = tid >> 5;          // 0..7 (+8*it)
    const int b_nq = (tid & 31) * 4;

    float4 a_reg[4], b_reg[4];

#define TG_LDG(KC)                                                                   \
    {                                                                                \
        _Pragma("unroll")                                                            \
        for (int it = 0; it < 4; it++) {                                             \
            a_reg[it] = *(const float4*)&A[(size_t)(rb + a_r + it*32) * K + (KC) + a_kq]; \
            b_reg[it] = *(const float4*)&B[(size_t)((KC) + b_k + it*8) * N + cb + b_nq];  \
        }                                                                            \
    }

#define TG_STS(BUF)                                                                 \
    {                                                                                \
        float* ap = As + (BUF) * AS_FLOATS;                                          \
        float* bp = Bs + (BUF) * BS_FLOATS;                                          \
        _Pragma("unroll")                                                            \
        for (int it = 0; it < 4; it++) {                                             \
            *(float4*)&ap[(a_r + it*32) * AS_STR + a_kq] = a_reg[it];                \
            *(float4*)&bp[(b_k + it*8)  * BS_STR + b_nq] = b_reg[it];                \
        }                                                                            \
    }

    TG_LDG(0);
    TG_STS(0);
    __syncthreads();

    int buf = 0;
    for (int kc = 0; kc < K; kc += 32) {
        const bool last = (kc + 32) >= K;
        if (!last) TG_LDG(kc + 32);

        const float* ap = As + buf * AS_FLOATS;
        const float* bp = Bs + buf * BS_FLOATS;
#pragma unroll
        for (int k8 = 0; k8 < 32; k8 += 8) {
            unsigned ah[2][4], al[2][4];
#pragma unroll
            for (int mt = 0; mt < 2; mt++) {
#pragma unroll
                for (int i = 0; i < 4; i++) {
                    const int r = m_w + mt*16 + (lane >> 2) + (i & 1) * 8;
                    const int c = k8 + (lane & 3) + (i >> 1) * 4;
                    const float f = ap[r * AS_STR + c];
                    const unsigned h = f2tf32(f);
                    ah[mt][i] = h;
                    al[mt][i] = f2tf32(f - __uint_as_float(h));
                }
            }
#pragma unroll
            for (int nt = 0; nt < 8; nt++) {
                const int n = n_w + nt*8 + (lane >> 2);
                const int k = k8 + (lane & 3);
                const float f0 = bp[k * BS_STR + n];
                const float f1 = bp[(k + 4) * BS_STR + n];
                unsigned bh[2], bl[2];
                bh[0] = f2tf32(f0); bl[0] = f2tf32(f0 - __uint_as_float(bh[0]));
                bh[1] = f2tf32(f1); bl[1] = f2tf32(f1 - __uint_as_float(bh[1]));
#pragma unroll
                for (int mt = 0; mt < 2; mt++) {
                    mma_tf32(acc[mt][nt], al[mt], bh);
                    mma_tf32(acc[mt][nt], ah[mt], bl);
                    mma_tf32(acc[mt][nt], ah[mt], bh);
                }
            }
        }

        if (!last) {
            TG_STS(buf ^ 1);
            __syncthreads();
            buf ^= 1;
        }
    }

    // epilogue
#pragma unroll
    for (int nt = 0; nt < 8; nt++) {
        const int col = cb + n_w + nt*8 + (lane & 3) * 2;
        float s0 = 1.f, s1 = 1.f, t0 = 0.f, t1 = 0.f;
        const float pb0 = bias[col], pb1 = bias[col + 1];
        if (epi == 1) {
            const float i0 = rsqrtf(var[col] + EPSBN);
            const float i1 = rsqrtf(var[col + 1] + EPSBN);
            s0 = gam[col] * i0;     t0 = bet[col]     - mu[col]     * s0;
            s1 = gam[col + 1] * i1; t1 = bet[col + 1] - mu[col + 1] * s1;
        }
#pragma unroll
        for (int mt = 0; mt < 2; mt++) {
            const int r0 = rb + m_w + mt*16 + (lane >> 2);
#pragma unroll
            for (int half = 0; half < 2; half++) {
                const int r = r0 + half * 8;
                float v0 = acc[mt][nt][half*2 + 0] + pb0;
                float v1 = acc[mt][nt][half*2 + 1] + pb1;
                if (epi == 1) {
                    v0 = gelu_exact(v0 * s0 + t0);
                    v1 = gelu_exact(v1 * s1 + t1);
                }
                *(float2*)&C[(size_t)r * N + col] = make_float2(v0, v1);
            }
        }
    }
#undef TG_LDG
#undef TG_STS
}

// ---------------- fused GATv2 edge kernel ----------------
// grid (HEADS, B), 1024 threads (32 warps). Phase 1 warp-per-edge (conflict-free
// contiguous row reads, att in registers, 4 edges in flight). Phase 2 unchanged.
#define SM_STRIDE 68
#define GAT_SMEM_FLOATS (2*Nn*SM_STRIDE + 64 + 2*Eg + (Nn+1))
__global__ __launch_bounds__(1024)
void gat_kernel(const float* __restrict__ xl, const float* __restrict__ xr,
                const float* __restrict__ att, const float* __restrict__ bo,
                const int* __restrict__ srce, const int* __restrict__ dste,
                const int* __restrict__ off,
                float* __restrict__ out)
{
    extern __shared__ float sm[];
    float*  s_xl   = sm;
    float*  s_xr   = sm + Nn*SM_STRIDE;
    float*  s_att  = sm + 2*Nn*SM_STRIDE;
    float2* s_pair = (float2*)(s_att + 64);
    int*    s_off  = (int*)(s_att + 64 + 2*Eg);

    const int h    = blockIdx.x;
    const int b    = blockIdx.y;
    const int tid  = threadIdx.x;
    const int nthr = 1024;
    const int warp = tid >> 5, lane = tid & 31;

    const float* xlb = xl + (size_t)b * Nn * HID + h * Ch;
    const float* xrb = xr + (size_t)b * Nn * HID + h * Ch;

    for (int i = tid; i < Nn * (Ch/4); i += nthr) {
        int n = i >> 4, c4 = i & 15;
        float4 lv = *(const float4*)(xlb + (size_t)n * HID + 4*c4);
        float4 rv = *(const float4*)(xrb + (size_t)n * HID + 4*c4);
        *(float4*)&s_xl[n*SM_STRIDE + 4*c4] = lv;
        *(float4*)&s_xr[n*SM_STRIDE + 4*c4] = rv;
    }
    if (tid < Ch) s_att[tid] = att[h * Ch + tid];
    if (tid >= nthr - (Nn+1)) s_off[tid - (nthr - (Nn+1))] = off[tid - (nthr - (Nn+1))];
    __syncthreads();

    // ---- phase 1: warp per edge, 4 edges in flight ----
    const float at0 = s_att[2*lane];
    const float at1 = s_att[2*lane + 1];
    const int4* srce4 = (const int4*)srce;
    const int4* dste4 = (const int4*)dste;

    for (int g = warp; g < Eg/4; g += 32) {
        const int4 s4 = srce4[g];
        const int4 d4 = dste4[g];
        float a0, a1, a2, a3;
        {
            float2 lv, rv; float v0, v1;
#define EDGE_LOGIT(SS, DD, OUTV)                                             \
            lv = *(const float2*)&s_xl[(SS)*SM_STRIDE + 2*lane];             \
            rv = *(const float2*)&s_xr[(DD)*SM_STRIDE + 2*lane];             \
            v0 = lv.x + rv.x; v0 = v0 > 0.f ? v0 : NEGS * v0;                \
            v1 = lv.y + rv.y; v1 = v1 > 0.f ? v1 : NEGS * v1;                \
            OUTV = fmaf(v1, at1, v0 * at0);
            EDGE_LOGIT(s4.x, d4.x, a0)
            EDGE_LOGIT(s4.y, d4.y, a1)
            EDGE_LOGIT(s4.z, d4.z, a2)
            EDGE_LOGIT(s4.w, d4.w, a3)
#undef EDGE_LOGIT
        }
#pragma unroll
        for (int o = 16; o; o >>= 1) {
            a0 += __shfl_xor_sync(0xffffffffu, a0, o);
            a1 += __shfl_xor_sync(0xffffffffu, a1, o);
            a2 += __shfl_xor_sync(0xffffffffu, a2, o);
            a3 += __shfl_xor_sync(0xffffffffu, a3, o);
        }
        if (lane == 0) {
            s_pair[4*g + 0] = make_float2(a0, __int_as_float(s4.x * SM_STRIDE));
            s_pair[4*g + 1] = make_float2(a1, __int_as_float(s4.y * SM_STRIDE));
            s_pair[4*g + 2] = make_float2(a2, __int_as_float(s4.z * SM_STRIDE));
            s_pair[4*g + 3] = make_float2(a3, __int_as_float(s4.w * SM_STRIDE));
        }
    }
    __syncthreads();

    // ---- phase 2: warp per node; half-warp per edge, float4 channels ----
    const int cg = lane & 15;
    const int ep = lane >> 4;
    const float4 bo4 = *(const float4*)(bo + h*Ch + 4*cg);

    for (int n = warp; n < Nn; n += 32) {
        const int o0  = s_off[n];
        const int deg = s_off[n+1] - o0;

        float m = -INFINITY;
        for (int i = lane; i < deg; i += 32) m = fmaxf(m, s_pair[o0 + i].x);
#pragma unroll
        for (int d = 16; d; d >>= 1) m = fmaxf(m, __shfl_xor_sync(0xffffffffu, m, d));

        float ssum = 0.f;
        for (int i = lane; i < deg; i += 32) ssum += expf(s_pair[o0 + i].x - m);
#pragma unroll
        for (int d = 16; d; d >>= 1) ssum += __shfl_xor_sync(0xffffffffu, ssum, d);
        const float inv = 1.0f / (ssum + 1e-16f);

        for (int i = lane; i < deg; i += 32)
            s_pair[o0 + i].x = expf(s_pair[o0 + i].x - m) * inv;
        __syncwarp();

        float4 acc = make_float4(0.f, 0.f, 0.f, 0.f);
#pragma unroll 4
        for (int j = ep; j < deg; j += 2) {
            const float2 p = s_pair[o0 + j];
            const int soff = __float_as_int(p.y);
            const float4 xv = *(const float4*)&s_xl[soff + 4*cg];
            acc.x = fmaf(p.x, xv.x, acc.x);
            acc.y = fmaf(p.x, xv.y, acc.y);
            acc.z = fmaf(p.x, xv.z, acc.z);
            acc.w = fmaf(p.x, xv.w, acc.w);
        }
        acc.x += __shfl_down_sync(0xffffffffu, acc.x, 16);
        acc.y += __shfl_down_sync(0xffffffffu, acc.y, 16);
        acc.z += __shfl_down_sync(0xffffffffu, acc.z, 16);
        acc.w += __shfl_down_sync(0xffffffffu, acc.w, 16);

        if (ep == 0) {
            float4 r;
            r.x = gelu_exact(acc.x + bo4.x);
            r.y = gelu_exact(acc.y + bo4.y);
            r.z = gelu_exact(acc.z + bo4.z);
            r.w = gelu_exact(acc.w + bo4.w);
            *(float4*)(out + (size_t)(b*Nn + n) * HID + h*Ch + 4*cg) = r;
        }
    }
}

// ---------------- mean pool over nodes ----------------
__global__ __launch_bounds__(256)
void pool_kernel(const float* __restrict__ hin, float* __restrict__ p) {
    const int b = blockIdx.x, c = threadIdx.x;
    float s = 0.f;
    const float* base = hin + (size_t)b * Nn * HID + c;
    for (int n = 0; n < Nn; n++) s += base[(size_t)n * HID];
    p[b * HID + c] = s * (1.0f / Nn);
}

// ---------------- output proj + BN + gelu ----------------
__global__ __launch_bounds__(256)
void final_kernel(const float* __restrict__ p, const float* __restrict__ W2,
                  const float* __restrict__ b2,
                  const float* __restrict__ g2, const float* __restrict__ be2,
                  const float* __restrict__ m2, const float* __restrict__ v2,
                  float* __restrict__ out) {
    const int b = blockIdx.x, c = threadIdx.x;
    __shared__ float sp[HID];
    sp[c] = p[b * HID + c];
    __syncthreads();
    float acc = 0.f;
    for (int k = 0; k < HID; k++) acc = fmaf(sp[k], W2[(size_t)k * HID + c], acc);
    acc += b2[c];
    float inv = rsqrtf(v2[c] + EPSBN);
    acc = (acc - m2[c]) * inv * g2[c] + be2[c];
    out[b * HID + c] = gelu_exact(acc);
}

// ---------------- launch ----------------
extern "C" void kernel_launch(void* const* d_in, const int* in_sizes, int n_in,
                              void* d_out, int out_size) {
    const float* x    = (const float*)d_in[0];
    const int*   ei   = (const int*)  d_in[1];
    const float* W1   = (const float*)d_in[2];
    const float* b1   = (const float*)d_in[3];
    const float* g1   = (const float*)d_in[4];
    const float* be1  = (const float*)d_in[5];
    const float* m1   = (const float*)d_in[6];
    const float* v1   = (const float*)d_in[7];
    const float* Wl0  = (const float*)d_in[8];
    const float* bl0  = (const float*)d_in[9];
    const float* Wr0  = (const float*)d_in[10];
    const float* br0  = (const float*)d_in[11];
    const float* att0 = (const float*)d_in[12];
    const float* bo0  = (const float*)d_in[13];
    const float* Wl1  = (const float*)d_in[14];
    const float* bl1  = (const float*)d_in[15];
    const float* Wr1  = (const float*)d_in[16];
    const float* br1  = (const float*)d_in[17];
    const float* att1 = (const float*)d_in[18];
    const float* bo1  = (const float*)d_in[19];
    const float* W2   = (const float*)d_in[20];
    const float* b2   = (const float*)d_in[21];
    const float* g2   = (const float*)d_in[22];
    const float* be2  = (const float*)d_in[23];
    const float* m2   = (const float*)d_in[24];
    const float* v2   = (const float*)d_in[25];

    float *h, *xl, *xr, *h2, *pl;
    int *off, *srce, *dste;
    cudaGetSymbolAddress((void**)&h,    g_h);
    cudaGetSymbolAddress((void**)&xl,   g_xl);
    cudaGetSymbolAddress((void**)&xr,   g_xr);
    cudaGetSymbolAddress((void**)&h2,   g_h2);
    cudaGetSymbolAddress((void**)&pl,   g_pool);
    cudaGetSymbolAddress((void**)&off,  g_off);
    cudaGetSymbolAddress((void**)&srce, g_srce);
    cudaGetSymbolAddress((void**)&dste, g_dste);

    const int gat_smem = GAT_SMEM_FLOATS * (int)sizeof(float);
    cudaFuncSetAttribute(gat_kernel, cudaFuncAttributeMaxDynamicSharedMemorySize, gat_smem);
    cudaFuncSetAttribute(tgemm_kernel, cudaFuncAttributeMaxDynamicSharedMemorySize, TG_SMEM);

    build_csr_kernel<<<1, 256>>>(ei, off, srce, dste);

    // node_proj: h = gelu(BN(x @ W1 + b1))
    tgemm_kernel<<<dim3(HID/128, ROWS/128), 256, TG_SMEM>>>(
        x, W1, b1, h, 0, 0, 0, ROWS, HID, F_IN, g1, be1, m1, v1, 1, 0);
    // layer 0: xl = h@Wl0+bl0, xr = h@Wr0+br0
    tgemm_kernel<<<dim3(2*HID/128, ROWS/128), 256, TG_SMEM>>>(
        h, Wl0, bl0, xl, Wr0, br0, xr, ROWS, HID, HID, 0, 0, 0, 0, 0, 1);
    gat_kernel<<<dim3(HEADS, Bsz), 1024, gat_smem>>>(xl, xr, att0, bo0, srce, dste, off, h2);
    // layer 1
    tgemm_kernel<<<dim3(2*HID/128, ROWS/128), 256, TG_SMEM>>>(
        h2, Wl1, bl1, xl, Wr1, br1, xr, ROWS, HID, HID, 0, 0, 0, 0, 0, 1);
    gat_kernel<<<dim3(HEADS, Bsz), 1024, gat_smem>>>(xl, xr, att1, bo1, srce, dste, off, h);

    pool_kernel<<<Bsz, 256>>>(h, pl);
    final_kernel<<<Bsz, 256>>>(pl, W2, b2, g2, be2, m2, v2, (float*)d_out);
}

// round 5
// speedup vs baseline: 1.4116x; 1.4116x over previous
#include <cuda_runtime.h>
#include <cuda_fp16.h>
#include <cuda_bf16.h>
#include <math.h>

// ---------------- problem constants ----------------
#define Bsz   64
#define Nn    256
#define CT    3
#define HID   256
#define HEADS 4
#define Ch    64
#define Eg    8192
#define F_IN  (Nn*CT)
#define ROWS  (Bsz*Nn)
#define NEGS  0.2f
#define EPSBN 1e-5f

// ---------------- scratch ----------------
__device__ float g_h [ROWS*HID];
__device__ float g_xl[ROWS*HID];
__device__ float g_xr[ROWS*HID];
__device__ float g_h2[ROWS*HID];
__device__ float g_pool[Bsz*HID];
__device__ int   g_off[Nn+1];
__device__ int   g_srce[Eg];
__device__ int   g_dste[Eg];

__device__ __forceinline__ float gelu_exact(float x) { return x * normcdff(x); }

__device__ __forceinline__ unsigned h2u(__half2 h) { return *reinterpret_cast<unsigned*>(&h); }

__device__ __forceinline__ void mma_f16(float* c, const unsigned* a, const unsigned* b) {
    asm("mma.sync.aligned.m16n8k16.row.col.f32.f16.f16.f32 "
        "{%0,%1,%2,%3},{%4,%5,%6,%7},{%8,%9},{%0,%1,%2,%3};"
        : "+f"(c[0]), "+f"(c[1]), "+f"(c[2]), "+f"(c[3])
        : "r"(a[0]), "r"(a[1]), "r"(a[2]), "r"(a[3]), "r"(b[0]), "r"(b[1]));
}

// split a float2 into hi/lo half2 parts
__device__ __forceinline__ void split_h2(float2 f, unsigned& hi, unsigned& lo) {
    __half2 h = __float22half2_rn(f);
    float2 hf = __half22float2(h);
    __half2 l = __float22half2_rn(make_float2(f.x - hf.x, f.y - hf.y));
    hi = h2u(h); lo = h2u(l);
}

// ---------------- deterministic CSR build ----------------
__global__ __launch_bounds__(256)
void build_csr_kernel(const int* __restrict__ ei,
                      int* __restrict__ off,
                      int* __restrict__ srce, int* __restrict__ dste) {
    __shared__ int hist[8][Nn];
    __shared__ int s_loc[Eg];
    __shared__ int s_off[Nn+1];

    const int tid  = threadIdx.x;
    const int w    = tid >> 5;
    const int lane = tid & 31;
    const int* srcA = ei;
    const int* dstA = ei + Eg;

    for (int i = tid; i < 8 * Nn; i += 256) ((int*)hist)[i] = 0;
    __syncthreads();

    const int base = w * 1024;
#pragma unroll 1
    for (int g = 0; g < 32; g++) {
        const int e = base + g * 32 + lane;
        const int d = dstA[e];
        unsigned mask = __match_any_sync(0xffffffffu, d);
        int leader = __ffs(mask) - 1;
        int rank   = __popc(mask & ((1u << lane) - 1u));
        int cur    = hist[w][d];
        s_loc[e]   = cur + rank;
        __syncwarp();
        if (lane == leader) hist[w][d] = cur + __popc(mask);
        __syncwarp();
    }
    __syncthreads();

    __shared__ int tot[Nn];
    if (tid < Nn) {
        int run = 0;
#pragma unroll
        for (int ww = 0; ww < 8; ww++) {
            int c = hist[ww][tid];
            hist[ww][tid] = run;
            run += c;
        }
        tot[tid] = run;
    }
    __syncthreads();
    if (tid == 0) {
        int run = 0;
        for (int n = 0; n < Nn; n++) { s_off[n] = run; run += tot[n]; }
        s_off[Nn] = run;
    }
    __syncthreads();

    if (tid < Nn) off[tid] = s_off[tid];
    if (tid == 0) off[Nn] = s_off[Nn];

    for (int e = tid; e < Eg; e += 256) {
        const int d  = dstA[e];
        const int we = e >> 10;
        const int pos = s_off[d] + hist[we][d] + s_loc[e];
        srce[pos] = srcA[e];
        dste[pos] = d;
    }
}

// ---------------- tensor-core GEMM (fp16 2-term split, ~fp32 accuracy) ----------------
// CTA 128x128, k-chunk 32, 256 threads = 8 warps (4m x 2n), warp tile 32x64.
// mma.m16n8k16.f16.f32, 3 mmas per k16: ah*bh + ah*bl + al*bh  (al*bl ~2^-22 dropped)
// smem: A[2][128][40] fp32 m-major (float2 frags land 2-to-1 on bank pairs = floor)
//       B[2][32][132] fp32 k-major (scalar frags hit all 32 banks)
#define AS_STR 40
#define BS_STR 132
#define AS_FLOATS (128*AS_STR)
#define BS_FLOATS (32*BS_STR)
#define HG_SMEM ((2*AS_FLOATS + 2*BS_FLOATS) * 4)

__global__ __launch_bounds__(256)
void hgemm_kernel(const float* __restrict__ A,
                  const float* __restrict__ B,  const float* __restrict__ bias,  float* __restrict__ C,
                  const float* __restrict__ B2, const float* __restrict__ bias2, float* __restrict__ C2,
                  int M, int N, int K,
                  const float* __restrict__ gam, const float* __restrict__ bet,
                  const float* __restrict__ mu,  const float* __restrict__ var,
                  int epi, int dual)
{
    extern __shared__ float sm[];
    float* As = sm;
    float* Bs = sm + 2*AS_FLOATS;

    const int tid  = threadIdx.x;
    const int warp = tid >> 5;
    const int lane = tid & 31;
    const int gq   = lane >> 2;   // group id 0..7
    const int tq   = lane & 3;    // thread in group
    int bx = blockIdx.x;
    const int nblk = dual ? (gridDim.x >> 1) : gridDim.x;
    if (dual && bx >= nblk) {
        bx -= nblk;
        B = B2; bias = bias2; C = C2;
    }
    const int cb = bx * 128;
    const int rb = blockIdx.y * 128;

    const int m_w = (warp & 3) * 32;
    const int n_w = (warp >> 2) * 64;

    float acc[2][8][4];
#pragma unroll
    for (int mt = 0; mt < 2; mt++)
#pragma unroll
        for (int nt = 0; nt < 8; nt++)
#pragma unroll
            for (int i = 0; i < 4; i++) acc[mt][nt][i] = 0.f;

    const int a_r  = tid >> 3;
    const int a_kq = (tid & 7) * 4;
    const int b_k  = tid >> 5;
    const int b_nq = (tid & 31) * 4;

    float4 a_reg[4], b_reg[4];

#define HG_LDG(KC)                                                                        \
    {                                                                                     \
        _Pragma("unroll")                                                                 \
        for (int it = 0; it < 4; it++) {                                                  \
            a_reg[it] = *(const float4*)&A[(size_t)(rb + a_r + it*32) * K + (KC) + a_kq]; \
            b_reg[it] = *(const float4*)&B[(size_t)((KC) + b_k + it*8) * N + cb + b_nq];  \
        }                                                                                 \
    }

#define HG_STS(BUF)                                                                      \
    {                                                                                     \
        float* ap_ = As + (BUF) * AS_FLOATS;                                              \
        float* bp_ = Bs + (BUF) * BS_FLOATS;                                              \
        _Pragma("unroll")                                                                 \
        for (int it = 0; it < 4; it++) {                                                  \
            *(float4*)&ap_[(a_r + it*32) * AS_STR + a_kq] = a_reg[it];                    \
            *(float4*)&bp_[(b_k + it*8)  * BS_STR + b_nq] = b_reg[it];                    \
        }                                                                                 \
    }

    HG_LDG(0);
    HG_STS(0);
    __syncthreads();

    int buf = 0;
    for (int kc = 0; kc < K; kc += 32) {
        const bool last = (kc + 32) >= K;
        if (!last) HG_LDG(kc + 32);

        const float* ap = As + buf * AS_FLOATS;
        const float* bp = Bs + buf * BS_FLOATS;
#pragma unroll
        for (int k16 = 0; k16 < 32; k16 += 16) {
            unsigned ah[2][4], al[2][4];
#pragma unroll
            for (int mt = 0; mt < 2; mt++) {
                const int r0 = m_w + mt*16 + gq;
                float2 f0 = *(const float2*)&ap[(size_t)r0      * AS_STR + k16 + 2*tq];
                float2 f1 = *(const float2*)&ap[(size_t)(r0+8)  * AS_STR + k16 + 2*tq];
                float2 f2 = *(const float2*)&ap[(size_t)r0      * AS_STR + k16 + 2*tq + 8];
                float2 f3 = *(const float2*)&ap[(size_t)(r0+8)  * AS_STR + k16 + 2*tq + 8];
                split_h2(f0, ah[mt][0], al[mt][0]);
                split_h2(f1, ah[mt][1], al[mt][1]);
                split_h2(f2, ah[mt][2], al[mt][2]);
                split_h2(f3, ah[mt][3], al[mt][3]);
            }
#pragma unroll
            for (int nt = 0; nt < 8; nt++) {
                const int n = n_w + nt*8 + gq;
                const float v0 = bp[(size_t)(k16 + 2*tq    ) * BS_STR + n];
                const float v1 = bp[(size_t)(k16 + 2*tq + 1) * BS_STR + n];
                const float v2 = bp[(size_t)(k16 + 2*tq + 8) * BS_STR + n];
                const float v3 = bp[(size_t)(k16 + 2*tq + 9) * BS_STR + n];
                unsigned bh[2], bl[2];
                split_h2(make_float2(v0, v1), bh[0], bl[0]);
                split_h2(make_float2(v2, v3), bh[1], bl[1]);
#pragma unroll
                for (int mt = 0; mt < 2; mt++) {
                    mma_f16(acc[mt][nt], al[mt], bh);
                    mma_f16(acc[mt][nt], ah[mt], bl);
                    mma_f16(acc[mt][nt], ah[mt], bh);
                }
            }
        }

        if (!last) {
            HG_STS(buf ^ 1);
            __syncthreads();
            buf ^= 1;
        }
    }

    // epilogue (same frag layout as m16n8k8: c0,c1 -> row g cols 2t,2t+1; c2,c3 -> row g+8)
#pragma unroll
    for (int nt = 0; nt < 8; nt++) {
        const int col = cb + n_w + nt*8 + tq*2;
        float s0 = 1.f, s1 = 1.f, t0 = 0.f, t1 = 0.f;
        const float pb0 = bias[col], pb1 = bias[col + 1];
        if (epi == 1) {
            const float i0 = rsqrtf(var[col] + EPSBN);
            const float i1 = rsqrtf(var[col + 1] + EPSBN);
            s0 = gam[col] * i0;     t0 = bet[col]     - mu[col]     * s0;
            s1 = gam[col + 1] * i1; t1 = bet[col + 1] - mu[col + 1] * s1;
        }
#pragma unroll
        for (int mt = 0; mt < 2; mt++) {
            const int r0 = rb + m_w + mt*16 + gq;
#pragma unroll
            for (int half = 0; half < 2; half++) {
                const int r = r0 + half * 8;
                float v0 = acc[mt][nt][half*2 + 0] + pb0;
                float v1 = acc[mt][nt][half*2 + 1] + pb1;
                if (epi == 1) {
                    v0 = gelu_exact(v0 * s0 + t0);
                    v1 = gelu_exact(v1 * s1 + t1);
                }
                *(float2*)&C[(size_t)r * N + col] = make_float2(v0, v1);
            }
        }
    }
#undef HG_LDG
#undef HG_STS
}

// ---------------- fused GATv2 edge kernel (round-3 proven version) ----------------
// grid (HEADS, B), 512 threads, one (sample,head) per block, all data in smem.
#define SM_STRIDE 68
#define GAT_SMEM_FLOATS (2*Nn*SM_STRIDE + 64 + 2*Eg + (Nn+1))
__global__ __launch_bounds__(512)
void gat_kernel(const float* __restrict__ xl, const float* __restrict__ xr,
                const float* __restrict__ att, const float* __restrict__ bo,
                const int* __restrict__ srce, const int* __restrict__ dste,
                const int* __restrict__ off,
                float* __restrict__ out)
{
    extern __shared__ float sm[];
    float*  s_xl   = sm;
    float*  s_xr   = sm + Nn*SM_STRIDE;
    float*  s_att  = sm + 2*Nn*SM_STRIDE;
    float2* s_pair = (float2*)(s_att + 64);
    int*    s_off  = (int*)(s_att + 64 + 2*Eg);

    const int h    = blockIdx.x;
    const int b    = blockIdx.y;
    const int tid  = threadIdx.x;
    const int nthr = 512;

    const float* xlb = xl + (size_t)b * Nn * HID + h * Ch;
    const float* xrb = xr + (size_t)b * Nn * HID + h * Ch;

    for (int i = tid; i < Nn * (Ch/4); i += nthr) {
        int n = i >> 4, c4 = i & 15;
        float4 lv = *(const float4*)(xlb + (size_t)n * HID + 4*c4);
        float4 rv = *(const float4*)(xrb + (size_t)n * HID + 4*c4);
        *(float4*)&s_xl[n*SM_STRIDE + 4*c4] = lv;
        *(float4*)&s_xr[n*SM_STRIDE + 4*c4] = rv;
    }
    if (tid < Ch) s_att[tid] = att[h * Ch + tid];
    if (tid >= nthr - (Nn+1)) s_off[tid - (nthr - (Nn+1))] = off[tid - (nthr - (Nn+1))];
    __syncthreads();

    // ---- phase 1: logits in CSR order (thread per edge) ----
    for (int i = tid; i < Eg; i += nthr) {
        const int s = srce[i];
        const int d = dste[i];
        const float4* pl = (const float4*)&s_xl[s * SM_STRIDE];
        const float4* pr = (const float4*)&s_xr[d * SM_STRIDE];
        float accv = 0.f;
#pragma unroll
        for (int c4 = 0; c4 < 16; c4++) {
            const float4 a4 = *(const float4*)&s_att[4*c4];
            const float4 l4 = pl[c4];
            const float4 r4 = pr[c4];
            float v;
            v = l4.x + r4.x; v = v > 0.f ? v : NEGS * v; accv = fmaf(v, a4.x, accv);
            v = l4.y + r4.y; v = v > 0.f ? v : NEGS * v; accv = fmaf(v, a4.y, accv);
            v = l4.z + r4.z; v = v > 0.f ? v : NEGS * v; accv = fmaf(v, a4.z, accv);
            v = l4.w + r4.w; v = v > 0.f ? v : NEGS * v; accv = fmaf(v, a4.w, accv);
        }
        s_pair[i] = make_float2(accv, __int_as_float(s * SM_STRIDE));
    }
    __syncthreads();

    // ---- phase 2: warp per node; half-warp per edge, float4 channels ----
    const int warp = tid >> 5, lane = tid & 31;
    const int cg = lane & 15;
    const int ep = lane >> 4;
    const float4 bo4 = *(const float4*)(bo + h*Ch + 4*cg);

    for (int n = warp; n < Nn; n += 16) {
        const int o0  = s_off[n];
        const int deg = s_off[n+1] - o0;

        float m = -INFINITY;
        for (int i = lane; i < deg; i += 32) m = fmaxf(m, s_pair[o0 + i].x);
#pragma unroll
        for (int d = 16; d; d >>= 1) m = fmaxf(m, __shfl_xor_sync(0xffffffffu, m, d));

        float ssum = 0.f;
        for (int i = lane; i < deg; i += 32) ssum += expf(s_pair[o0 + i].x - m);
#pragma unroll
        for (int d = 16; d; d >>= 1) ssum += __shfl_xor_sync(0xffffffffu, ssum, d);
        const float inv = 1.0f / (ssum + 1e-16f);

        for (int i = lane; i < deg; i += 32)
            s_pair[o0 + i].x = expf(s_pair[o0 + i].x - m) * inv;
        __syncwarp();

        float4 acc = make_float4(0.f, 0.f, 0.f, 0.f);
#pragma unroll 4
        for (int j = ep; j < deg; j += 2) {
            const float2 p = s_pair[o0 + j];
            const int soff = __float_as_int(p.y);
            const float4 xv = *(const float4*)&s_xl[soff + 4*cg];
            acc.x = fmaf(p.x, xv.x, acc.x);
            acc.y = fmaf(p.x, xv.y, acc.y);
            acc.z = fmaf(p.x, xv.z, acc.z);
            acc.w = fmaf(p.x, xv.w, acc.w);
        }
        acc.x += __shfl_down_sync(0xffffffffu, acc.x, 16);
        acc.y += __shfl_down_sync(0xffffffffu, acc.y, 16);
        acc.z += __shfl_down_sync(0xffffffffu, acc.z, 16);
        acc.w += __shfl_down_sync(0xffffffffu, acc.w, 16);

        if (ep == 0) {
            float4 r;
            r.x = gelu_exact(acc.x + bo4.x);
            r.y = gelu_exact(acc.y + bo4.y);
            r.z = gelu_exact(acc.z + bo4.z);
            r.w = gelu_exact(acc.w + bo4.w);
            *(float4*)(out + (size_t)(b*Nn + n) * HID + h*Ch + 4*cg) = r;
        }
    }
}

// ---------------- mean pool over nodes ----------------
__global__ __launch_bounds__(256)
void pool_kernel(const float* __restrict__ hin, float* __restrict__ p) {
    const int b = blockIdx.x, c = threadIdx.x;
    float s = 0.f;
    const float* base = hin + (size_t)b * Nn * HID + c;
    for (int n = 0; n < Nn; n++) s += base[(size_t)n * HID];
    p[b * HID + c] = s * (1.0f / Nn);
}

// ---------------- output proj + BN + gelu ----------------
__global__ __launch_bounds__(256)
void final_kernel(const float* __restrict__ p, const float* __restrict__ W2,
                  const float* __restrict__ b2,
                  const float* __restrict__ g2, const float* __restrict__ be2,
                  const float* __restrict__ m2, const float* __restrict__ v2,
                  float* __restrict__ out) {
    const int b = blockIdx.x, c = threadIdx.x;
    __shared__ float sp[HID];
    sp[c] = p[b * HID + c];
    __syncthreads();
    float acc = 0.f;
    for (int k = 0; k < HID; k++) acc = fmaf(sp[k], W2[(size_t)k * HID + c], acc);
    acc += b2[c];
    float inv = rsqrtf(v2[c] + EPSBN);
    acc = (acc - m2[c]) * inv * g2[c] + be2[c];
    out[b * HID + c] = gelu_exact(acc);
}

// ---------------- launch ----------------
extern "C" void kernel_launch(void* const* d_in, const int* in_sizes, int n_in,
                              void* d_out, int out_size) {
    const float* x    = (const float*)d_in[0];
    const int*   ei   = (const int*)  d_in[1];
    const float* W1   = (const float*)d_in[2];
    const float* b1   = (const float*)d_in[3];
    const float* g1   = (const float*)d_in[4];
    const float* be1  = (const float*)d_in[5];
    const float* m1   = (const float*)d_in[6];
    const float* v1   = (const float*)d_in[7];
    const float* Wl0  = (const float*)d_in[8];
    const float* bl0  = (const float*)d_in[9];
    const float* Wr0  = (const float*)d_in[10];
    const float* br0  = (const float*)d_in[11];
    const float* att0 = (const float*)d_in[12];
    const float* bo0  = (const float*)d_in[13];
    const float* Wl1  = (const float*)d_in[14];
    const float* bl1  = (const float*)d_in[15];
    const float* Wr1  = (const float*)d_in[16];
    const float* br1  = (const float*)d_in[17];
    const float* att1 = (const float*)d_in[18];
    const float* bo1  = (const float*)d_in[19];
    const float* W2   = (const float*)d_in[20];
    const float* b2   = (const float*)d_in[21];
    const float* g2   = (const float*)d_in[22];
    const float* be2  = (const float*)d_in[23];
    const float* m2   = (const float*)d_in[24];
    const float* v2   = (const float*)d_in[25];

    float *h, *xl, *xr, *h2, *pl;
    int *off, *srce, *dste;
    cudaGetSymbolAddress((void**)&h,    g_h);
    cudaGetSymbolAddress((void**)&xl,   g_xl);
    cudaGetSymbolAddress((void**)&xr,   g_xr);
    cudaGetSymbolAddress((void**)&h2,   g_h2);
    cudaGetSymbolAddress((void**)&pl,   g_pool);
    cudaGetSymbolAddress((void**)&off,  g_off);
    cudaGetSymbolAddress((void**)&srce, g_srce);
    cudaGetSymbolAddress((void**)&dste, g_dste);

    const int gat_smem = GAT_SMEM_FLOATS * (int)sizeof(float);
    cudaFuncSetAttribute(gat_kernel, cudaFuncAttributeMaxDynamicSharedMemorySize, gat_smem);
    cudaFuncSetAttribute(hgemm_kernel, cudaFuncAttributeMaxDynamicSharedMemorySize, HG_SMEM);

    build_csr_kernel<<<1, 256>>>(ei, off, srce, dste);

    // node_proj: h = gelu(BN(x @ W1 + b1))
    hgemm_kernel<<<dim3(HID/128, ROWS/128), 256, HG_SMEM>>>(
        x, W1, b1, h, 0, 0, 0, ROWS, HID, F_IN, g1, be1, m1, v1, 1, 0);
    // layer 0: xl = h@Wl0+bl0, xr = h@Wr0+br0
    hgemm_kernel<<<dim3(2*HID/128, ROWS/128), 256, HG_SMEM>>>(
        h, Wl0, bl0, xl, Wr0, br0, xr, ROWS, HID, HID, 0, 0, 0, 0, 0, 1);
    gat_kernel<<<dim3(HEADS, Bsz), 512, gat_smem>>>(xl, xr, att0, bo0, srce, dste, off, h2);
    // layer 1
    hgemm_kernel<<<dim3(2*HID/128, ROWS/128), 256, HG_SMEM>>>(
        h2, Wl1, bl1, xl, Wr1, br1, xr, ROWS, HID, HID, 0, 0, 0, 0, 0, 1);
    gat_kernel<<<dim3(HEADS, Bsz), 512, gat_smem>>>(xl, xr, att1, bo1, srce, dste, off, h);

    pool_kernel<<<Bsz, 256>>>(h, pl);
    final_kernel<<<Bsz, 256>>>(pl, W2, b2, g2, be2, m2, v2, (float*)d_out);
}